// round 14
// baseline (speedup 1.0000x reference)
#include <cuda_runtime.h>

// BoundaryBCELoss: 5x clamped plus-dilation of two masks + BCE vs target, mean-reduced.
// Round 14: SINGLE kernel. (1) R13's PDL didn't overlap (graph capture likely rejected
// the attr -> plain serialized launch; 5.9us for an empty-queue kernel). The fallback
// is now INLINE: failing blocks recompute via an SMEM-based halo-5 pipeline (36.3KB
// ping-pong, unioned over xbuf -> no register growth, smem cap 6 CTAs/SM), and the
// finalization is a completion counter inside this kernel (atomics spread over 27
// waves; only the tail is exposed). (2) certificate fused into iteration 2: its
// values are never needed (pass -> p==1; fail -> fallback recomputes), so iter-2 is
// sums + running fminf over inner in-image cells, cert = (min >= 1.0f) == bitwise
// clamp==1 test. No clamp/pack/writeback/border-zero in iter-2, no separate cert pass.

#define W_IMG 384
#define H_IMG 384
#define N_IMG 64
#define TILE_X 60
#define TILE_Y 44
#define GRID_X 7             // ceil(384/60)
#define GRID_Y 9             // ceil(384/44)
#define NBLK (GRID_X * GRID_Y * N_IMG)   // 4032

// ---- fast path: halo 2, uniform bands ----
#define A_HALO 2
#define A_LX 64              // TILE_X + 4 (exactly 32 column pairs)
#define A_LY 48              // TILE_Y + 4 (exactly 6 rows per warp)
#define A_R 6

// ---- inline fallback: halo 5 (x-halo 6), SMEM-based, per 30-col half ----
#define B_HALF 30
#define B_HX 6
#define B_HY 5
#define B_LX 42              // 30 + 12
#define B_LY 54              // 44 + 10

#define NW 8
#define NTHREADS 256

typedef unsigned long long u64;

#define ADD_F32X2(o, a, b) \
    asm("add.rn.f32x2 %0, %1, %2;" : "=l"(o) : "l"(a), "l"(b))
#define PACK2(o, lo, hi) \
    asm("mov.b64 %0, {%1, %2};" : "=l"(o) : "f"(lo), "f"(hi))
#define UNPACK2(lo, hi, in) \
    asm("mov.b64 {%0, %1}, %2;" : "=f"(lo), "=f"(hi) : "l"(in))

__device__ float         g_accum = 0.0f;   // reset by finalizer each call
__device__ unsigned int  g_done  = 0;      // reset by finalizer each call

// SMEM union: fast path uses xbuf (16 KB); fallback reuses the same bytes as a
// 2x(54x42) float2 ping-pong (36,288 B). red[] is separate.
#define SMRAW_BYTES (2 * B_LX * B_LY * (int)sizeof(float2))   // 36288

// ---- inline fallback: one 30-col half, full halo-5 x 5-iteration recompute ----
__device__ float fallback_half(const float* __restrict__ hb,
                               const float* __restrict__ ob,
                               const float* __restrict__ tb,
                               int x0, int y0, float2* buf0, float2* buf1, int tid)
{
    // Stage 42x54 with zero padding outside the image.
    for (int idx = tid; idx < B_LX * B_LY; idx += NTHREADS) {
        const int r = idx / B_LX;
        const int c = idx - r * B_LX;
        const int gr = y0 + r;
        const int gc = x0 + c;
        float2 v = make_float2(0.0f, 0.0f);
        if ((unsigned)gr < H_IMG && (unsigned)gc < W_IMG) {
            v.x = hb[gr * W_IMG + gc];
            v.y = ob[gr * W_IMG + gc];
        }
        buf0[idx] = v;
    }
    __syncthreads();

    // 5 dilation iterations over the shrinking valid region [k, L-k).
    #pragma unroll 1
    for (int k = 1; k <= 5; k++) {
        float2* src = (k & 1) ? buf0 : buf1;
        float2* dst = (k & 1) ? buf1 : buf0;
        for (int r = k + (tid >> 5); r < B_LY - k; r += NW) {
            for (int c = k + (tid & 31); c < B_LX - k; c += 32) {
                const float2 m  = src[r * B_LX + c];
                const float2 u  = src[(r - 1) * B_LX + c];
                const float2 d  = src[(r + 1) * B_LX + c];
                const float2 l  = src[r * B_LX + c - 1];
                const float2 rr = src[r * B_LX + c + 1];
                float sx = fminf(m.x + u.x + d.x + l.x + rr.x, 1.0f);
                float sy = fminf(m.y + u.y + d.y + l.y + rr.y, 1.0f);
                // Reference zero-pads EVERY conv.
                const bool in = ((unsigned)(y0 + r) < H_IMG) &&
                                ((unsigned)(x0 + c) < W_IMG);
                dst[r * B_LX + c] = in ? make_float2(sx, sy)
                                       : make_float2(0.0f, 0.0f);
            }
        }
        __syncthreads();
    }

    // Full BCE over this half's inner region (result in buf1 after k=5).
    float lsum = 0.0f;
    for (int idx = tid; idx < B_HALF * TILE_Y; idx += NTHREADS) {
        const int r = B_HY + idx / B_HALF;
        const int c = B_HX + idx % B_HALF;
        const int gr = y0 + r;
        const int gc = x0 + c;
        if ((unsigned)gr < H_IMG && (unsigned)gc < W_IMG) {
            const float2 v = buf1[r * B_LX + c];
            const float p = v.x * v.y;
            const float t = tb[gr * W_IMG + gc];
            float contrib;
            if (p >= 1.0f) {
                contrib = -100.0f * (1.0f - t);
            } else {
                const float lp  = fmaxf(logf(p), -100.0f);
                const float l1p = fmaxf(logf(1.0f - p), -100.0f);
                contrib = t * lp + (1.0f - t) * l1p;
            }
            lsum += contrib;
        }
    }
    __syncthreads();     // buffers reused by the next half
    return lsum;
}

// ============================ The single kernel ============================
__global__ __launch_bounds__(NTHREADS) void bce_kernel(
    const float* __restrict__ hand,
    const float* __restrict__ obj,
    const float* __restrict__ target,
    float* __restrict__ out)
{
    __shared__ __align__(16) char smraw[SMRAW_BYTES];
    __shared__ float red[NW];
    u64 (*xbuf)[2][NW][32][2] = (u64(*)[2][NW][32][2])smraw;

    const int n   = blockIdx.z;
    const int y0  = blockIdx.y * TILE_Y - A_HALO;
    const int x0  = blockIdx.x * TILE_X - A_HALO;        // even
    const int tid = threadIdx.x;
    const int w   = tid >> 5;
    const int pl  = tid & 31;

    const int r_lo = A_R * w;                             // uniform 6 rows/warp

    const int  gx     = x0 + 2 * pl;                      // pair {gx, gx+1} in or out
    const bool col_in = ((unsigned)gx < W_IMG);           // x0 even => pair-uniform
    const bool interior = (x0 >= 0) && (y0 >= 0) &&
                          (x0 + A_LX <= W_IMG) && (y0 + A_LY <= H_IMG);

    const size_t img = (size_t)n * H_IMG * W_IMG;
    const float* hb = hand + img;
    const float* ob = obj + img;
    const float* tb = target + img;

    // ---- Stage band rows into registers; prefetch target rows to L2 ----
    u64 ra[A_R], rb[A_R];
    #pragma unroll
    for (int i = 0; i < A_R; i++) { ra[i] = 0; rb[i] = 0; }

    #pragma unroll
    for (int i = 0; i < A_R; i++) {
        const int rl = r_lo + i;
        const int gy = y0 + rl;
        if (col_in && (unsigned)gy < H_IMG) {
            const float2 hh = *(const float2*)(hb + gy * W_IMG + gx);
            const float2 oo = *(const float2*)(ob + gy * W_IMG + gx);
            PACK2(ra[i], hh.x, oo.x);
            PACK2(rb[i], hh.y, oo.y);
        }
        if (((pl & 15) == 1) && rl >= A_HALO && rl < A_HALO + TILE_Y &&
            col_in && (unsigned)gy < H_IMG)
            asm volatile("prefetch.global.L2 [%0];"
                         :: "l"(tb + gy * W_IMG + gx));
    }

    // ---- Iteration 1: full clamped dilation h0 -> h1 (writeback) ----
    {
        *(ulonglong2*)&(*xbuf)[0][w][pl][0] = make_ulonglong2(ra[0], rb[0]);
        *(ulonglong2*)&(*xbuf)[1][w][pl][0] = make_ulonglong2(ra[A_R - 1], rb[A_R - 1]);
        __syncthreads();

        u64 pa = 0, pb = 0, na = 0, nb = 0;
        if (w > 0) {
            ulonglong2 v = *(ulonglong2*)&(*xbuf)[1][w - 1][pl][0];
            pa = v.x; pb = v.y;
        }
        if (w < NW - 1) {
            ulonglong2 v = *(ulonglong2*)&(*xbuf)[0][w + 1][pl][0];
            na = v.x; nb = v.y;
        }

        #pragma unroll
        for (int i = 0; i < A_R; i++) {
            const u64 ca = ra[i], cb = rb[i];
            const u64 xa = (i + 1 < A_R) ? ra[i + 1] : na;
            const u64 xb = (i + 1 < A_R) ? rb[i + 1] : nb;
            const u64 lf = __shfl_up_sync(0xffffffffu, cb, 1);   // col 2pl-1
            const u64 rt = __shfl_down_sync(0xffffffffu, ca, 1); // col 2pl+2

            u64 t, s0, s1;
            ADD_F32X2(t, ca, cb);
            ADD_F32X2(s0, t, lf);
            ADD_F32X2(s0, s0, pa);
            ADD_F32X2(s0, s0, xa);
            ADD_F32X2(s1, t, rt);
            ADD_F32X2(s1, s1, pb);
            ADD_F32X2(s1, s1, xb);

            float a0, a1, b0, b1;
            UNPACK2(a0, a1, s0);
            UNPACK2(b0, b1, s1);
            a0 = fminf(a0, 1.0f); a1 = fminf(a1, 1.0f);
            b0 = fminf(b0, 1.0f); b1 = fminf(b1, 1.0f);

            if (!interior) {
                // Re-zero out-of-image cells: reference zero-pads EVERY conv.
                const bool rin = (unsigned)(y0 + r_lo + i) < H_IMG;
                const bool in  = rin && col_in;
                a0 = in ? a0 : 0.0f;  a1 = in ? a1 : 0.0f;
                b0 = in ? b0 : 0.0f;  b1 = in ? b1 : 0.0f;
            }

            pa = ca; pb = cb;
            PACK2(ra[i], a0, a1);
            PACK2(rb[i], b0, b1);
        }
        __syncthreads();    // xbuf parity-0/1 both reused next phase
    }

    // ---- Iteration 2 fused with certificate: sums of h1 + running min over
    //      inner in-image cells. h2==1 everywhere <=> min(sums) >= 1. Values
    //      themselves are never needed (pass -> p==1; fail -> fallback). ----
    float mn = 2.0f;
    {
        *(ulonglong2*)&(*xbuf)[0][w][pl][0] = make_ulonglong2(ra[0], rb[0]);
        *(ulonglong2*)&(*xbuf)[1][w][pl][0] = make_ulonglong2(ra[A_R - 1], rb[A_R - 1]);
        __syncthreads();

        u64 pa = 0, pb = 0, na = 0, nb = 0;
        if (w > 0) {
            ulonglong2 v = *(ulonglong2*)&(*xbuf)[1][w - 1][pl][0];
            pa = v.x; pb = v.y;
        }
        if (w < NW - 1) {
            ulonglong2 v = *(ulonglong2*)&(*xbuf)[0][w + 1][pl][0];
            na = v.x; nb = v.y;
        }

        const bool lane_inner = (pl >= 1 && pl <= 30) && col_in;

        #pragma unroll
        for (int i = 0; i < A_R; i++) {
            const u64 ca = ra[i], cb = rb[i];
            const u64 xa = (i + 1 < A_R) ? ra[i + 1] : na;
            const u64 xb = (i + 1 < A_R) ? rb[i + 1] : nb;
            const u64 lf = __shfl_up_sync(0xffffffffu, cb, 1);
            const u64 rt = __shfl_down_sync(0xffffffffu, ca, 1);

            u64 t, s0, s1;
            ADD_F32X2(t, ca, cb);
            ADD_F32X2(s0, t, lf);
            ADD_F32X2(s0, s0, pa);
            ADD_F32X2(s0, s0, xa);
            ADD_F32X2(s1, t, rt);
            ADD_F32X2(s1, s1, pb);
            ADD_F32X2(s1, s1, xb);

            const int rl = r_lo + i;
            if (lane_inner && rl >= A_HALO && rl < A_HALO + TILE_Y &&
                (unsigned)(y0 + rl) < H_IMG) {
                float a0, a1, b0, b1;
                UNPACK2(a0, a1, s0);
                UNPACK2(b0, b1, s1);
                mn = fminf(mn, fminf(fminf(a0, a1), fminf(b0, b1)));
            }

            pa = ca; pb = cb;
        }
    }

    const bool pass = __syncthreads_and(mn >= 1.0f);

    float lsum;
    if (pass) {
        // ---- BCE with p==1 everywhere: contrib = -100*(1-t) (target in L2) ----
        u64 tacc = 0;
        int cells = 0;
        if (pl >= 1 && pl <= 30 && col_in) {
            #pragma unroll
            for (int i = 0; i < A_R; i++) {
                const int rl = r_lo + i;
                const int gy = y0 + rl;
                if (rl >= A_HALO && rl < A_HALO + TILE_Y && (unsigned)gy < H_IMG) {
                    const u64 t2 = *(const u64*)(tb + gy * W_IMG + gx);
                    ADD_F32X2(tacc, tacc, t2);
                    cells += 2;
                }
            }
        }
        float tlo, thi;
        UNPACK2(tlo, thi, tacc);
        lsum = -100.0f * ((float)cells - tlo - thi);
    } else {
        // ---- Inline fallback: full halo-5 recompute, two 30-col halves.
        //      SMEM-based (reuses smraw; xbuf is dead past the barrier above). ----
        float2* b0 = (float2*)smraw;
        float2* b1 = b0 + B_LX * B_LY;
        const int fy0 = blockIdx.y * TILE_Y - B_HY;
        const int fx0 = blockIdx.x * TILE_X - B_HX;          // even
        __syncthreads();    // everyone past cert before overwriting smraw
        lsum  = fallback_half(hb, ob, tb, fx0,          fy0, b0, b1, tid);
        lsum += fallback_half(hb, ob, tb, fx0 + B_HALF, fy0, b0, b1, tid);
    }

    // ---- Block reduction + global accumulate ----
    #pragma unroll
    for (int off = 16; off > 0; off >>= 1)
        lsum += __shfl_down_sync(0xffffffffu, lsum, off);

    if (pl == 0) red[w] = lsum;
    __syncthreads();

    if (tid < NW) {
        float v = red[tid];
        #pragma unroll
        for (int off = NW / 2; off > 0; off >>= 1)
            v += __shfl_down_sync((1u << NW) - 1u, v, off);
        if (tid == 0) atomicAdd(&g_accum, v);
    }

    // ---- Completion: last of NBLK blocks finalizes and resets state ----
    if (tid == 0) {
        __threadfence();
        const unsigned old = atomicAdd(&g_done, 1u);
        if (old == NBLK - 1) {
            __threadfence();
            const float a = *((volatile float*)&g_accum);
            const float inv_total = 1.0f / ((float)N_IMG * H_IMG * W_IMG);
            *out = -a * inv_total;
            g_accum = 0.0f;      // clean state for the next graph replay
            g_done  = 0u;
            __threadfence();
        }
    }
}

extern "C" void kernel_launch(void* const* d_in, const int* in_sizes, int n_in,
                              void* d_out, int out_size)
{
    const float* hand   = (const float*)d_in[0];
    const float* obj    = (const float*)d_in[1];
    const float* target = (const float*)d_in[2];
    float* out = (float*)d_out;

    dim3 grid(GRID_X, GRID_Y, N_IMG);    // 7 x 9 x 64 = 4032 blocks
    bce_kernel<<<grid, NTHREADS>>>(hand, obj, target, out);
}

// round 15
// speedup vs baseline: 1.1070x; 1.1070x over previous
#include <cuda_runtime.h>

// BoundaryBCELoss: 5x clamped plus-dilation of two masks + BCE vs target, mean-reduced.
// Round 15: single kernel WITHOUT R14's occupancy penalties. R14 lost to regs 54
// (4 CTAs) + 36KB static smem; the second launch in R11-13 had a hard ~5.9us floor.
// Here: (1) smem stays 16KB (xbuf only) -- the rare fallback uses a __device__ GLOBAL
// scratch ping-pong, run ONLY by the completion-elected last block over a failure
// queue (expected empty); (2) __launch_bounds__(256,5) caps regs at 51 (5 CTAs/SM,
// mild 3-reg squeeze vs R14's natural 54); (3) fused iter-2 certificate kept: iter-2
// computes sums + running fminf over inner in-image cells only (values never needed:
// pass -> p==1 BCE; fail -> fallback recomputes from h0), cert = min >= 1.0f.

#define W_IMG 384
#define H_IMG 384
#define N_IMG 64
#define TILE_X 60
#define TILE_Y 44
#define GRID_X 7             // ceil(384/60)
#define GRID_Y 9             // ceil(384/44)
#define NBLK (GRID_X * GRID_Y * N_IMG)   // 4032

// ---- fast path: halo 2, uniform bands ----
#define A_HALO 2
#define A_LX 64              // TILE_X + 4 (exactly 32 column pairs)
#define A_LY 48              // TILE_Y + 4 (exactly 6 rows per warp)
#define A_R 6

// ---- fallback (last block only, global scratch): halo 5 (x-halo 6), full tile ----
#define B_HX 6
#define B_HY 5
#define B_LX 72              // TILE_X + 12
#define B_LY 54              // TILE_Y + 10

#define NW 8
#define NTHREADS 256

typedef unsigned long long u64;

#define ADD_F32X2(o, a, b) \
    asm("add.rn.f32x2 %0, %1, %2;" : "=l"(o) : "l"(a), "l"(b))
#define PACK2(o, lo, hi) \
    asm("mov.b64 %0, {%1, %2};" : "=l"(o) : "f"(lo), "f"(hi))
#define UNPACK2(lo, hi, in) \
    asm("mov.b64 {%0, %1}, %2;" : "=f"(lo), "=f"(hi) : "l"(in))

__device__ int          g_list[NBLK];        // failed-bid queue
__device__ int          g_nfail = 0;         // reset by finalizer
__device__ float        g_accum = 0.0f;      // reset by finalizer
__device__ unsigned int g_done  = 0;         // reset by finalizer
__device__ float2       g_scr[2 * B_LX * B_LY];   // finalizer's fallback scratch

// ---- fallback: one failed 60-wide tile, full halo-5 x 5-iteration recompute in
//      GLOBAL scratch. Executed by the single finalize block (expected never). ----
__device__ float fb_tile_loss(const float* __restrict__ hb,
                              const float* __restrict__ ob,
                              const float* __restrict__ tb,
                              int x0, int y0, int tid)
{
    float2* b0 = g_scr;
    float2* b1 = g_scr + B_LX * B_LY;

    // Stage 72x54 with zero padding outside the image.
    for (int idx = tid; idx < B_LX * B_LY; idx += NTHREADS) {
        const int r = idx / B_LX;
        const int c = idx - r * B_LX;
        const int gr = y0 + r;
        const int gc = x0 + c;
        float2 v = make_float2(0.0f, 0.0f);
        if ((unsigned)gr < H_IMG && (unsigned)gc < W_IMG) {
            v.x = hb[gr * W_IMG + gc];
            v.y = ob[gr * W_IMG + gc];
        }
        b0[idx] = v;
    }
    __syncthreads();

    // 5 dilation iterations over the shrinking valid region [k, L-k).
    #pragma unroll 1
    for (int k = 1; k <= 5; k++) {
        float2* src = (k & 1) ? b0 : b1;
        float2* dst = (k & 1) ? b1 : b0;
        for (int r = k + (tid >> 5); r < B_LY - k; r += NW) {
            for (int c = k + (tid & 31); c < B_LX - k; c += 32) {
                const float2 m  = src[r * B_LX + c];
                const float2 u  = src[(r - 1) * B_LX + c];
                const float2 d  = src[(r + 1) * B_LX + c];
                const float2 l  = src[r * B_LX + c - 1];
                const float2 rr = src[r * B_LX + c + 1];
                float sx = fminf(m.x + u.x + d.x + l.x + rr.x, 1.0f);
                float sy = fminf(m.y + u.y + d.y + l.y + rr.y, 1.0f);
                const bool in = ((unsigned)(y0 + r) < H_IMG) &&
                                ((unsigned)(x0 + c) < W_IMG);
                dst[r * B_LX + c] = in ? make_float2(sx, sy)
                                       : make_float2(0.0f, 0.0f);
            }
        }
        __syncthreads();
    }

    // Full BCE over the tile's inner region (result in b1 after k=5).
    float lsum = 0.0f;
    for (int idx = tid; idx < TILE_X * TILE_Y; idx += NTHREADS) {
        const int r = B_HY + idx / TILE_X;
        const int c = B_HX + idx % TILE_X;
        const int gr = y0 + r;
        const int gc = x0 + c;
        if ((unsigned)gr < H_IMG && (unsigned)gc < W_IMG) {
            const float2 v = b1[r * B_LX + c];
            const float p = v.x * v.y;
            const float t = tb[gr * W_IMG + gc];
            float contrib;
            if (p >= 1.0f) {
                contrib = -100.0f * (1.0f - t);
            } else {
                const float lp  = fmaxf(logf(p), -100.0f);
                const float l1p = fmaxf(logf(1.0f - p), -100.0f);
                contrib = t * lp + (1.0f - t) * l1p;
            }
            lsum += contrib;
        }
    }
    __syncthreads();     // scratch reused by the next queue entry
    return lsum;
}

// ============================ The single kernel ============================
__global__ __launch_bounds__(NTHREADS, 5) void bce_kernel(
    const float* __restrict__ hand,
    const float* __restrict__ obj,
    const float* __restrict__ target,
    float* __restrict__ out)
{
    __shared__ __align__(16) u64 xbuf[2][2][NW][32][2];   // 16 KB
    __shared__ float red[NW];
    __shared__ int s_last;

    const int n   = blockIdx.z;
    const int y0  = blockIdx.y * TILE_Y - A_HALO;
    const int x0  = blockIdx.x * TILE_X - A_HALO;        // even
    const int tid = threadIdx.x;
    const int w   = tid >> 5;
    const int pl  = tid & 31;
    const int bid = (blockIdx.z * GRID_Y + blockIdx.y) * GRID_X + blockIdx.x;

    const int r_lo = A_R * w;                             // uniform 6 rows/warp

    const int  gx     = x0 + 2 * pl;                      // pair {gx, gx+1} in or out
    const bool col_in = ((unsigned)gx < W_IMG);           // x0 even => pair-uniform
    const bool interior = (x0 >= 0) && (y0 >= 0) &&
                          (x0 + A_LX <= W_IMG) && (y0 + A_LY <= H_IMG);

    const size_t img = (size_t)n * H_IMG * W_IMG;
    const float* hb = hand + img;
    const float* ob = obj + img;
    const float* tb = target + img;

    // ---- Stage band rows into registers; prefetch target rows to L2 ----
    u64 ra[A_R], rb[A_R];
    #pragma unroll
    for (int i = 0; i < A_R; i++) { ra[i] = 0; rb[i] = 0; }

    #pragma unroll
    for (int i = 0; i < A_R; i++) {
        const int rl = r_lo + i;
        const int gy = y0 + rl;
        if (col_in && (unsigned)gy < H_IMG) {
            const float2 hh = *(const float2*)(hb + gy * W_IMG + gx);
            const float2 oo = *(const float2*)(ob + gy * W_IMG + gx);
            PACK2(ra[i], hh.x, oo.x);
            PACK2(rb[i], hh.y, oo.y);
        }
        if (((pl & 15) == 1) && rl >= A_HALO && rl < A_HALO + TILE_Y &&
            col_in && (unsigned)gy < H_IMG)
            asm volatile("prefetch.global.L2 [%0];"
                         :: "l"(tb + gy * W_IMG + gx));
    }

    // ---- Iteration 1: full clamped dilation h0 -> h1 (writeback) ----
    {
        *(ulonglong2*)&xbuf[0][0][w][pl][0] = make_ulonglong2(ra[0], rb[0]);
        *(ulonglong2*)&xbuf[0][1][w][pl][0] = make_ulonglong2(ra[A_R - 1], rb[A_R - 1]);
        __syncthreads();

        u64 pa = 0, pb = 0, na = 0, nb = 0;
        if (w > 0) {
            ulonglong2 v = *(ulonglong2*)&xbuf[0][1][w - 1][pl][0];
            pa = v.x; pb = v.y;
        }
        if (w < NW - 1) {
            ulonglong2 v = *(ulonglong2*)&xbuf[0][0][w + 1][pl][0];
            na = v.x; nb = v.y;
        }

        #pragma unroll
        for (int i = 0; i < A_R; i++) {
            const u64 ca = ra[i], cb = rb[i];
            const u64 xa = (i + 1 < A_R) ? ra[i + 1] : na;
            const u64 xb = (i + 1 < A_R) ? rb[i + 1] : nb;
            const u64 lf = __shfl_up_sync(0xffffffffu, cb, 1);   // col 2pl-1
            const u64 rt = __shfl_down_sync(0xffffffffu, ca, 1); // col 2pl+2

            u64 t, s0, s1;
            ADD_F32X2(t, ca, cb);
            ADD_F32X2(s0, t, lf);
            ADD_F32X2(s0, s0, pa);
            ADD_F32X2(s0, s0, xa);
            ADD_F32X2(s1, t, rt);
            ADD_F32X2(s1, s1, pb);
            ADD_F32X2(s1, s1, xb);

            float a0, a1, b0, b1;
            UNPACK2(a0, a1, s0);
            UNPACK2(b0, b1, s1);
            a0 = fminf(a0, 1.0f); a1 = fminf(a1, 1.0f);
            b0 = fminf(b0, 1.0f); b1 = fminf(b1, 1.0f);

            if (!interior) {
                // Re-zero out-of-image cells: reference zero-pads EVERY conv.
                const bool rin = (unsigned)(y0 + r_lo + i) < H_IMG;
                const bool in  = rin && col_in;
                a0 = in ? a0 : 0.0f;  a1 = in ? a1 : 0.0f;
                b0 = in ? b0 : 0.0f;  b1 = in ? b1 : 0.0f;
            }

            pa = ca; pb = cb;
            PACK2(ra[i], a0, a1);
            PACK2(rb[i], b0, b1);
        }
        __syncthreads();    // both xbuf slots reused next phase
    }

    // ---- Iteration 2 fused with certificate: sums of h1 + running min over
    //      inner in-image cells. h2==1 everywhere <=> min(sums) >= 1. ----
    float mn = 2.0f;
    {
        *(ulonglong2*)&xbuf[1][0][w][pl][0] = make_ulonglong2(ra[0], rb[0]);
        *(ulonglong2*)&xbuf[1][1][w][pl][0] = make_ulonglong2(ra[A_R - 1], rb[A_R - 1]);
        __syncthreads();

        u64 pa = 0, pb = 0, na = 0, nb = 0;
        if (w > 0) {
            ulonglong2 v = *(ulonglong2*)&xbuf[1][1][w - 1][pl][0];
            pa = v.x; pb = v.y;
        }
        if (w < NW - 1) {
            ulonglong2 v = *(ulonglong2*)&xbuf[1][0][w + 1][pl][0];
            na = v.x; nb = v.y;
        }

        const bool lane_inner = (pl >= 1 && pl <= 30) && col_in;

        #pragma unroll
        for (int i = 0; i < A_R; i++) {
            const u64 ca = ra[i], cb = rb[i];
            const u64 xa = (i + 1 < A_R) ? ra[i + 1] : na;
            const u64 xb = (i + 1 < A_R) ? rb[i + 1] : nb;
            const u64 lf = __shfl_up_sync(0xffffffffu, cb, 1);
            const u64 rt = __shfl_down_sync(0xffffffffu, ca, 1);

            u64 t, s0, s1;
            ADD_F32X2(t, ca, cb);
            ADD_F32X2(s0, t, lf);
            ADD_F32X2(s0, s0, pa);
            ADD_F32X2(s0, s0, xa);
            ADD_F32X2(s1, t, rt);
            ADD_F32X2(s1, s1, pb);
            ADD_F32X2(s1, s1, xb);

            const int rl = r_lo + i;
            if (lane_inner && rl >= A_HALO && rl < A_HALO + TILE_Y &&
                (unsigned)(y0 + rl) < H_IMG) {
                float a0, a1, b0, b1;
                UNPACK2(a0, a1, s0);
                UNPACK2(b0, b1, s1);
                mn = fminf(mn, fminf(fminf(a0, a1), fminf(b0, b1)));
            }

            pa = ca; pb = cb;
        }
    }

    const bool pass = __syncthreads_and(mn >= 1.0f);

    float lsum = 0.0f;
    if (pass) {
        // ---- BCE with p==1 everywhere: contrib = -100*(1-t) (target in L2) ----
        u64 tacc = 0;
        int cells = 0;
        if (pl >= 1 && pl <= 30 && col_in) {
            #pragma unroll
            for (int i = 0; i < A_R; i++) {
                const int rl = r_lo + i;
                const int gy = y0 + rl;
                if (rl >= A_HALO && rl < A_HALO + TILE_Y && (unsigned)gy < H_IMG) {
                    const u64 t2 = *(const u64*)(tb + gy * W_IMG + gx);
                    ADD_F32X2(tacc, tacc, t2);
                    cells += 2;
                }
            }
        }
        float tlo, thi;
        UNPACK2(tlo, thi, tacc);
        lsum = -100.0f * ((float)cells - tlo - thi);
    } else {
        // Push this tile onto the failure queue; the finalize block recomputes it.
        if (tid == 0) {
            const int pos = atomicAdd(&g_nfail, 1);
            g_list[pos] = bid;
        }
    }

    // ---- Block reduction + global accumulate (fail blocks contribute 0) ----
    #pragma unroll
    for (int off = 16; off > 0; off >>= 1)
        lsum += __shfl_down_sync(0xffffffffu, lsum, off);

    if (pl == 0) red[w] = lsum;
    __syncthreads();

    if (tid == 0) {
        float v = 0.0f;
        #pragma unroll
        for (int i = 0; i < NW; i++) v += red[i];
        atomicAdd(&g_accum, v);
        // Completion: queue/accum writes fenced before the counter bump.
        __threadfence();
        s_last = (atomicAdd(&g_done, 1u) == NBLK - 1) ? 1 : 0;
        if (s_last) __threadfence();     // acquire side for queue reads below
    }
    __syncthreads();

    // ---- Finalize block: process failure queue (expected empty), write out ----
    if (s_last) {
        const int nf = *((volatile int*)&g_nfail);
        float fsum = 0.0f;
        for (int q = 0; q < nf; q++) {
            const int b  = g_list[q];
            const int bx = b % GRID_X;
            const int by = (b / GRID_X) % GRID_Y;
            const int nn = b / (GRID_X * GRID_Y);
            const size_t im2 = (size_t)nn * H_IMG * W_IMG;
            fsum += fb_tile_loss(hand + im2, obj + im2, target + im2,
                                 bx * TILE_X - B_HX, by * TILE_Y - B_HY, tid);
        }

        #pragma unroll
        for (int off = 16; off > 0; off >>= 1)
            fsum += __shfl_down_sync(0xffffffffu, fsum, off);
        if (pl == 0) red[w] = fsum;
        __syncthreads();

        if (tid == 0) {
            float v = 0.0f;
            #pragma unroll
            for (int i = 0; i < NW; i++) v += red[i];
            const float a = *((volatile float*)&g_accum);
            const float inv_total = 1.0f / ((float)N_IMG * H_IMG * W_IMG);
            *out = -(a + v) * inv_total;
            g_accum = 0.0f;      // clean state for the next graph replay
            g_nfail = 0;
            g_done  = 0u;
            __threadfence();
        }
    }
}

extern "C" void kernel_launch(void* const* d_in, const int* in_sizes, int n_in,
                              void* d_out, int out_size)
{
    const float* hand   = (const float*)d_in[0];
    const float* obj    = (const float*)d_in[1];
    const float* target = (const float*)d_in[2];
    float* out = (float*)d_out;

    dim3 grid(GRID_X, GRID_Y, N_IMG);    // 7 x 9 x 64 = 4032 blocks
    bce_kernel<<<grid, NTHREADS>>>(hand, obj, target, out);
}